// round 3
// baseline (speedup 1.0000x reference)
#include <cuda_runtime.h>
#include <math.h>

#define B_ 8
#define C_ 128
#define N_ 4096

// Scratch (allocation-free requirement -> __device__ globals)
__device__ float g_q[B_*C_*N_];
__device__ float g_k[B_*C_*N_];
__device__ float g_v[B_*C_*N_];
__device__ float g_o[B_*C_*N_];

// ---------------------------------------------------------------------------
// Projection kernel: out[b,o,n] = sum_c w[o,c] * (X[b,c,n] * fw[c]) + bias[o]
// Computes up to 3 projections from one staged X tile (QKV fused).
// Grid: (N_/128, B_), 256 threads. Each thread: 8x8 micro-tile.
// ---------------------------------------------------------------------------
__global__ __launch_bounds__(256) void proj_kernel(
    const float* __restrict__ X, const float* __restrict__ fw,
    const float* __restrict__ w0, const float* __restrict__ b0, float* __restrict__ o0,
    const float* __restrict__ w1, const float* __restrict__ b1, float* __restrict__ o1,
    const float* __restrict__ w2, const float* __restrict__ b2, float* __restrict__ o2)
{
    extern __shared__ float xs[];          // [128][132] padded
    const int b  = blockIdx.y;
    const int nt = blockIdx.x * 128;
    const int t  = threadIdx.x;

    const float* xb = X + (size_t)b*C_*N_ + nt;
    if (fw) {
        for (int e = t; e < C_*128; e += 256) {
            int c = e >> 7, n = e & 127;
            xs[c*132 + n] = xb[(size_t)c*N_ + n] * fw[c];
        }
    } else {
        for (int e = t; e < C_*128; e += 256) {
            int c = e >> 7, n = e & 127;
            xs[c*132 + n] = xb[(size_t)c*N_ + n];
        }
    }
    __syncthreads();

    const int to = (t >> 4) * 8;   // output-channel base (0..120)
    const int tn = (t & 15) * 8;   // token base          (0..120)

    const float* Wp[3] = {w0, w1, w2};
    const float* Bp[3] = {b0, b1, b2};
    float*       Op[3] = {o0, o1, o2};

    for (int p = 0; p < 3; p++) {
        if (!Wp[p]) break;
        const float* w = Wp[p];
        float acc[8][8];
        #pragma unroll
        for (int oo = 0; oo < 8; oo++) {
            float bb = Bp[p][to + oo];
            #pragma unroll
            for (int nn = 0; nn < 8; nn++) acc[oo][nn] = bb;
        }
        #pragma unroll 4
        for (int c = 0; c < C_; c++) {
            float4 xa = *(const float4*)&xs[c*132 + tn];
            float4 xc = *(const float4*)&xs[c*132 + tn + 4];
            float xr[8] = {xa.x, xa.y, xa.z, xa.w, xc.x, xc.y, xc.z, xc.w};
            #pragma unroll
            for (int oo = 0; oo < 8; oo++) {
                float wv = __ldg(&w[(to+oo)*C_ + c]);
                #pragma unroll
                for (int nn = 0; nn < 8; nn++)
                    acc[oo][nn] = fmaf(wv, xr[nn], acc[oo][nn]);
            }
        }
        float* ob = Op[p] + (size_t)b*C_*N_ + nt;
        #pragma unroll
        for (int oo = 0; oo < 8; oo++) {
            *(float4*)&ob[(size_t)(to+oo)*N_ + tn]
                = make_float4(acc[oo][0],acc[oo][1],acc[oo][2],acc[oo][3]);
            *(float4*)&ob[(size_t)(to+oo)*N_ + tn + 4]
                = make_float4(acc[oo][4],acc[oo][5],acc[oo][6],acc[oo][7]);
        }
    }
}

// ---------------------------------------------------------------------------
// Flash attention, fp32, online softmax.
// Grid: (N_/64 q-tiles, B_), 256 threads.
// Thread (ti,tj), ti=t/16, tj=t%16:
//   S phase : rows i = ti*4+ii (4), cols j = tj*4+jj (4)  -> 16 accum
//   PV phase: rows i = ti*4+ii (4), dims d = dd*16+tj (8) -> 32 accum
// Qs/Ks d-major [128][64]; Vs [64][129] (transposed, conflict-free);
// Ps [64][68].
// ---------------------------------------------------------------------------
#define QS_OFF 0
#define KS_OFF 8192
#define VS_OFF 16384
#define PS_OFF 24640
#define ATTN_SMEM_FLOATS 28992   // 115968 bytes

__global__ __launch_bounds__(256) void attn_kernel()
{
    extern __shared__ float sm[];
    float* Qs = sm + QS_OFF;
    float* Ks = sm + KS_OFF;
    float* Vs = sm + VS_OFF;
    float* Ps = sm + PS_OFF;

    const int b  = blockIdx.y;
    const int mt = blockIdx.x * 64;
    const int t  = threadIdx.x;
    const int ti = t >> 4;     // 0..15
    const int tj = t & 15;     // 0..15

    const float* q = g_q + (size_t)b*C_*N_;
    const float* k = g_k + (size_t)b*C_*N_;
    const float* v = g_v + (size_t)b*C_*N_;

    // fold 1/sqrt(C) and log2(e) into Q so softmax uses exp2f
    const float QSCALE = 0.08838834764831845f * 1.4426950408889634f;

    for (int e = t; e < C_*64; e += 256) {
        int d = e >> 6, i = e & 63;
        Qs[d*64 + i] = q[(size_t)d*N_ + mt + i] * QSCALE;
    }

    float m_[4], l_[4], o_[4][8];
    #pragma unroll
    for (int ii = 0; ii < 4; ii++) {
        m_[ii] = -1e30f; l_[ii] = 0.0f;
        #pragma unroll
        for (int dd = 0; dd < 8; dd++) o_[ii][dd] = 0.0f;
    }

    for (int kt = 0; kt < N_/64; kt++) {
        const int n0 = kt * 64;
        __syncthreads();   // prev PV done reading Vs/Ps
        for (int e = t; e < C_*64; e += 256) {
            int d = e >> 6, j = e & 63;
            float kv = k[(size_t)d*N_ + n0 + j];
            float vv = v[(size_t)d*N_ + n0 + j];
            Ks[d*64 + j]  = kv;
            Vs[j*129 + d] = vv;
        }
        __syncthreads();

        // S = Q^T K (scaled)
        float s[4][4];
        #pragma unroll
        for (int ii = 0; ii < 4; ii++)
            #pragma unroll
            for (int jj = 0; jj < 4; jj++) s[ii][jj] = 0.0f;

        #pragma unroll 4
        for (int d = 0; d < C_; d++) {
            float4 q4 = *(const float4*)&Qs[d*64 + ti*4];
            float4 k4 = *(const float4*)&Ks[d*64 + tj*4];
            float qr[4] = {q4.x, q4.y, q4.z, q4.w};
            float kr[4] = {k4.x, k4.y, k4.z, k4.w};
            #pragma unroll
            for (int ii = 0; ii < 4; ii++)
                #pragma unroll
                for (int jj = 0; jj < 4; jj++)
                    s[ii][jj] = fmaf(qr[ii], kr[jj], s[ii][jj]);
        }

        // Online softmax per row (reduce across the 16 tj lanes of this ti)
        #pragma unroll
        for (int ii = 0; ii < 4; ii++) {
            float mx = fmaxf(fmaxf(s[ii][0], s[ii][1]), fmaxf(s[ii][2], s[ii][3]));
            #pragma unroll
            for (int off = 1; off < 16; off <<= 1)
                mx = fmaxf(mx, __shfl_xor_sync(0xffffffffu, mx, off));
            float mnew  = fmaxf(m_[ii], mx);
            float scale = exp2f(m_[ii] - mnew);
            m_[ii] = mnew;

            float rs = 0.0f;
            #pragma unroll
            for (int jj = 0; jj < 4; jj++) {
                s[ii][jj] = exp2f(s[ii][jj] - mnew);
                rs += s[ii][jj];
            }
            #pragma unroll
            for (int off = 1; off < 16; off <<= 1)
                rs += __shfl_xor_sync(0xffffffffu, rs, off);
            l_[ii] = l_[ii] * scale + rs;
            #pragma unroll
            for (int dd = 0; dd < 8; dd++) o_[ii][dd] *= scale;

            *(float4*)&Ps[(ti*4+ii)*68 + tj*4]
                = make_float4(s[ii][0], s[ii][1], s[ii][2], s[ii][3]);
        }
        __syncthreads();   // Ps visible to all

        // O += P * V
        #pragma unroll 2
        for (int j = 0; j < 64; j++) {
            float vr[8];
            #pragma unroll
            for (int dd = 0; dd < 8; dd++) vr[dd] = Vs[j*129 + dd*16 + tj];
            #pragma unroll
            for (int ii = 0; ii < 4; ii++) {
                float p = Ps[(ti*4+ii)*68 + j];
                #pragma unroll
                for (int dd = 0; dd < 8; dd++)
                    o_[ii][dd] = fmaf(p, vr[dd], o_[ii][dd]);
            }
        }
    }

    float* ob = g_o + (size_t)b*C_*N_ + mt;
    #pragma unroll
    for (int ii = 0; ii < 4; ii++) {
        float inv = 1.0f / l_[ii];
        #pragma unroll
        for (int dd = 0; dd < 8; dd++)
            ob[(size_t)(dd*16+tj)*N_ + ti*4 + ii] = o_[ii][dd] * inv;
    }
}

// ---------------------------------------------------------------------------
extern "C" void kernel_launch(void* const* d_in, const int* in_sizes, int n_in,
                              void* d_out, int out_size)
{
    const float* x  = (const float*)d_in[0];
    const float* fw = (const float*)d_in[1];
    const float* wq = (const float*)d_in[2];
    const float* bq = (const float*)d_in[3];
    const float* wk = (const float*)d_in[4];
    const float* bk = (const float*)d_in[5];
    const float* wv = (const float*)d_in[6];
    const float* bv = (const float*)d_in[7];
    const float* wo = (const float*)d_in[8];
    const float* bo = (const float*)d_in[9];
    float* out = (float*)d_out;

    float *qp, *kp, *vp, *op;
    cudaGetSymbolAddress((void**)&qp, g_q);
    cudaGetSymbolAddress((void**)&kp, g_k);
    cudaGetSymbolAddress((void**)&vp, g_v);
    cudaGetSymbolAddress((void**)&op, g_o);

    const int proj_smem = 128*132*sizeof(float);          // 67584
    const int attn_smem = ATTN_SMEM_FLOATS*sizeof(float); // 115968
    cudaFuncSetAttribute(proj_kernel, cudaFuncAttributeMaxDynamicSharedMemorySize, proj_smem);
    cudaFuncSetAttribute(attn_kernel, cudaFuncAttributeMaxDynamicSharedMemorySize, attn_smem);

    dim3 pg(N_/128, B_);
    // QKV projections with fw folded in (FFT stage == fw[c]*x, exact identity)
    proj_kernel<<<pg, 256, proj_smem>>>(x, fw,
                                        wq, bq, qp,
                                        wk, bk, kp,
                                        wv, bv, vp);
    dim3 ag(N_/64, B_);
    attn_kernel<<<ag, 256, attn_smem>>>();
    // Output projection
    proj_kernel<<<pg, 256, proj_smem>>>(op, nullptr,
                                        wo, bo, out,
                                        nullptr, nullptr, nullptr,
                                        nullptr, nullptr, nullptr);
}

// round 5
// speedup vs baseline: 4.8484x; 4.8484x over previous
#include <cuda_runtime.h>
#include <cuda_bf16.h>
#include <stdint.h>

#define B_ 8
#define C_ 128
#define N_ 4096

// ---------------------------------------------------------------------------
// Scratch: bf16 hi/lo operands, all [B][N][C]; attention out fp32 [B][N][C]
// ---------------------------------------------------------------------------
__device__ __nv_bfloat16 g_qh[B_*N_*C_];
__device__ __nv_bfloat16 g_ql[B_*N_*C_];
__device__ __nv_bfloat16 g_kh[B_*N_*C_];
__device__ __nv_bfloat16 g_kl[B_*N_*C_];
__device__ __nv_bfloat16 g_vh[B_*N_*C_];
__device__ __nv_bfloat16 g_vl[B_*N_*C_];
__device__ float         g_o [B_*N_*C_];

// fold 1/sqrt(C) * log2(e) into Q so softmax uses exp2
#define QSCALE (0.08838834764831845f * 1.4426950408889634f)

// ---------------------------------------------------------------------------
// PTX helpers (base-target instructions only: sm_80-era)
// ---------------------------------------------------------------------------
__device__ __forceinline__ uint32_t smem_u32(const void* p) {
    uint32_t a;
    asm("{ .reg .u64 t; cvta.to.shared.u64 t, %1; cvt.u32.u64 %0, t; }" : "=r"(a) : "l"(p));
    return a;
}
__device__ __forceinline__ void ldsm4(uint32_t* r, uint32_t a) {
    asm volatile("ldmatrix.sync.aligned.m8n8.x4.shared.b16 {%0,%1,%2,%3}, [%4];"
        : "=r"(r[0]), "=r"(r[1]), "=r"(r[2]), "=r"(r[3]) : "r"(a));
}
__device__ __forceinline__ void ldsm4t(uint32_t* r, uint32_t a) {
    asm volatile("ldmatrix.sync.aligned.m8n8.x4.trans.shared.b16 {%0,%1,%2,%3}, [%4];"
        : "=r"(r[0]), "=r"(r[1]), "=r"(r[2]), "=r"(r[3]) : "r"(a));
}
__device__ __forceinline__ void mma16816(float* c, const uint32_t* a,
                                         uint32_t b0, uint32_t b1) {
    asm volatile("mma.sync.aligned.m16n8k16.row.col.f32.bf16.bf16.f32 "
        "{%0,%1,%2,%3}, {%4,%5,%6,%7}, {%8,%9}, {%0,%1,%2,%3};"
        : "+f"(c[0]), "+f"(c[1]), "+f"(c[2]), "+f"(c[3])
        : "r"(a[0]), "r"(a[1]), "r"(a[2]), "r"(a[3]), "r"(b0), "r"(b1));
}
// pack two f32 -> bf16x2 (lo -> lower half, hi -> upper half)
__device__ __forceinline__ uint32_t packbf(float lo, float hi) {
    uint32_t r;
    asm("cvt.rn.bf16x2.f32 %0, %1, %2;" : "=r"(r) : "f"(hi), "f"(lo));
    return r;
}
__device__ __forceinline__ float ex2f(float x) {
    float y; asm("ex2.approx.ftz.f32 %0, %1;" : "=f"(y) : "f"(x)); return y;
}
#define CP_ASYNC16(d, g) \
    asm volatile("cp.async.cg.shared.global [%0], [%1], 16;" :: "r"(d), "l"(g) : "memory")
#define CP_COMMIT()  asm volatile("cp.async.commit_group;" ::: "memory")
#define CP_WAIT1()   asm volatile("cp.async.wait_group 1;" ::: "memory")
#define CP_WAIT0()   asm volatile("cp.async.wait_group 0;" ::: "memory")

// ---------------------------------------------------------------------------
// QKV projection: out = W*(fw.*x) + b, emitted as [B][N][C] bf16 hi/lo.
// Grid (N_/128, B_), 256 threads, 8x8 micro-tiles.
// ---------------------------------------------------------------------------
__global__ __launch_bounds__(256) void proj_qkv_kernel(
    const float* __restrict__ X, const float* __restrict__ fw,
    const float* __restrict__ wq, const float* __restrict__ bq,
    const float* __restrict__ wk, const float* __restrict__ bk,
    const float* __restrict__ wv, const float* __restrict__ bv)
{
    extern __shared__ float xs[];          // [128][132]
    const int b  = blockIdx.y;
    const int nt = blockIdx.x * 128;
    const int t  = threadIdx.x;

    const float* xb = X + (size_t)b*C_*N_ + nt;
    for (int e = t; e < C_*128; e += 256) {
        int c = e >> 7, n = e & 127;
        xs[c*132 + n] = xb[(size_t)c*N_ + n] * fw[c];
    }
    __syncthreads();

    const int to = (t >> 4) * 8;
    const int tn = (t & 15) * 8;

    const float* Wp[3] = {wq, wk, wv};
    const float* Bp[3] = {bq, bk, bv};
    __nv_bfloat16* Oh[3] = {g_qh, g_kh, g_vh};
    __nv_bfloat16* Ol[3] = {g_ql, g_kl, g_vl};

    for (int p = 0; p < 3; p++) {
        const float* w = Wp[p];
        float acc[8][8];
        #pragma unroll
        for (int oo = 0; oo < 8; oo++) {
            float bb = Bp[p][to + oo];
            #pragma unroll
            for (int nn = 0; nn < 8; nn++) acc[oo][nn] = bb;
        }
        #pragma unroll 4
        for (int c = 0; c < C_; c++) {
            float4 xa = *(const float4*)&xs[c*132 + tn];
            float4 xc = *(const float4*)&xs[c*132 + tn + 4];
            float xr[8] = {xa.x, xa.y, xa.z, xa.w, xc.x, xc.y, xc.z, xc.w};
            #pragma unroll
            for (int oo = 0; oo < 8; oo++) {
                float wv_ = __ldg(&w[(to+oo)*C_ + c]);
                #pragma unroll
                for (int nn = 0; nn < 8; nn++)
                    acc[oo][nn] = fmaf(wv_, xr[nn], acc[oo][nn]);
            }
        }
        const float sc = (p == 0) ? QSCALE : 1.0f;
        #pragma unroll
        for (int nn = 0; nn < 8; nn++) {
            union { unsigned short u[8]; uint4 v; } H, L;
            #pragma unroll
            for (int oo = 0; oo < 8; oo++) {
                float vv = acc[oo][nn] * sc;
                __nv_bfloat16 hb = __float2bfloat16(vv);
                __nv_bfloat16 lb = __float2bfloat16(vv - __bfloat162float(hb));
                H.u[oo] = __bfloat16_as_ushort(hb);
                L.u[oo] = __bfloat16_as_ushort(lb);
            }
            size_t off = ((size_t)b*N_ + nt + tn + nn)*C_ + to;
            *(uint4*)(Oh[p] + off) = H.v;
            *(uint4*)(Ol[p] + off) = L.v;
        }
    }
}

// ---------------------------------------------------------------------------
// Output projection: X is [B][N][C] fp32 (attention out); out[b,o,n] (BCHW).
// ---------------------------------------------------------------------------
__global__ __launch_bounds__(256) void proj_out_kernel(
    const float* __restrict__ X,
    const float* __restrict__ w0, const float* __restrict__ b0,
    float* __restrict__ o0)
{
    extern __shared__ float xs[];          // [c][n] 128x132
    const int b  = blockIdx.y;
    const int nt = blockIdx.x * 128;
    const int t  = threadIdx.x;

    const float* xb = X + ((size_t)b*N_ + nt)*C_;
    for (int e = t; e < 4096; e += 256) {      // 128 rows x 32 float4
        int n = e >> 5, c4 = e & 31;
        float4 v = *(const float4*)(xb + (size_t)n*C_ + c4*4);
        xs[(c4*4+0)*132 + n] = v.x;
        xs[(c4*4+1)*132 + n] = v.y;
        xs[(c4*4+2)*132 + n] = v.z;
        xs[(c4*4+3)*132 + n] = v.w;
    }
    __syncthreads();

    const int to = (t >> 4) * 8;
    const int tn = (t & 15) * 8;

    float acc[8][8];
    #pragma unroll
    for (int oo = 0; oo < 8; oo++) {
        float bb = b0[to + oo];
        #pragma unroll
        for (int nn = 0; nn < 8; nn++) acc[oo][nn] = bb;
    }
    #pragma unroll 4
    for (int c = 0; c < C_; c++) {
        float4 xa = *(const float4*)&xs[c*132 + tn];
        float4 xc = *(const float4*)&xs[c*132 + tn + 4];
        float xr[8] = {xa.x, xa.y, xa.z, xa.w, xc.x, xc.y, xc.z, xc.w};
        #pragma unroll
        for (int oo = 0; oo < 8; oo++) {
            float wv_ = __ldg(&w0[(to+oo)*C_ + c]);
            #pragma unroll
            for (int nn = 0; nn < 8; nn++)
                acc[oo][nn] = fmaf(wv_, xr[nn], acc[oo][nn]);
        }
    }
    float* ob = o0 + (size_t)b*C_*N_ + nt;
    #pragma unroll
    for (int oo = 0; oo < 8; oo++) {
        *(float4*)&ob[(size_t)(to+oo)*N_ + tn]
            = make_float4(acc[oo][0],acc[oo][1],acc[oo][2],acc[oo][3]);
        *(float4*)&ob[(size_t)(to+oo)*N_ + tn + 4]
            = make_float4(acc[oo][4],acc[oo][5],acc[oo][6],acc[oo][7]);
    }
}

// ---------------------------------------------------------------------------
// mma.sync flash attention (split-bf16, unnormalized O accumulation).
// Grid (N_/128, B_), 256 threads (8 warps x m16 query rows).
// SMEM layout (bytes), row stride 272 (conflict-free ldmatrix):
//   Qh 0, Ql 34816                      (128 rows x 256B data)
//   KV stages at 69632 + s*69632: Kh +0, Kl +17408, Vh +34816, Vl +52224
//   (64 rows each). Total 208896.
// ---------------------------------------------------------------------------
#define KROW   272
#define SM_QL  34816
#define SM_KV  69632
#define STAGE  69632
#define ATTN_SMEM 208896

__device__ __forceinline__ void kv_prefetch(uint32_t dstb, int tid,
    const __nv_bfloat16* kh, const __nv_bfloat16* kl,
    const __nv_bfloat16* vh, const __nv_bfloat16* vl, int n0)
{
    const __nv_bfloat16* srcs[4] = {kh, kl, vh, vl};
    #pragma unroll
    for (int sub = 0; sub < 4; sub++) {
        const __nv_bfloat16* s = srcs[sub];
        #pragma unroll
        for (int j = 0; j < 4; j++) {
            int idx = tid + j*256;           // 0..1023: 64 rows x 16 chunks
            int r = idx >> 4, c = idx & 15;
            uint32_t d = dstb + sub*17408 + r*KROW + c*16;
            CP_ASYNC16(d, s + (size_t)(n0 + r)*C_ + c*8);
        }
    }
}

__global__ __launch_bounds__(256, 1) void attn_mma_kernel()
{
    extern __shared__ char sm[];
    const uint32_t sb = smem_u32(sm);
    const int tid  = threadIdx.x;
    const int lane = tid & 31;
    const int w    = tid >> 5;
    const int b    = blockIdx.y;
    const int q0   = blockIdx.x * 128;
    const int lm8  = lane & 7;
    const int t8   = lane >> 3;

    const __nv_bfloat16* qh_b = g_qh + ((size_t)b*N_ + q0)*C_;
    const __nv_bfloat16* ql_b = g_ql + ((size_t)b*N_ + q0)*C_;
    const __nv_bfloat16* kh_b = g_kh + (size_t)b*N_*C_;
    const __nv_bfloat16* kl_b = g_kl + (size_t)b*N_*C_;
    const __nv_bfloat16* vh_b = g_vh + (size_t)b*N_*C_;
    const __nv_bfloat16* vl_b = g_vl + (size_t)b*N_*C_;

    // stage Q (hi/lo), prefetch KV tile 0
    for (int e = tid; e < 2048; e += 256) {          // 128 rows x 16 chunks
        int r = e >> 4, c = e & 15;
        *(uint4*)(sm + r*KROW + c*16)         = *(const uint4*)(qh_b + (size_t)r*C_ + c*8);
        *(uint4*)(sm + SM_QL + r*KROW + c*16) = *(const uint4*)(ql_b + (size_t)r*C_ + c*8);
    }
    kv_prefetch(sb + SM_KV, tid, kh_b, kl_b, vh_b, vl_b, 0);
    CP_COMMIT();
    __syncthreads();

    // per-thread ldmatrix address components
    const uint32_t q_addr = sb + (w*16 + (t8&1)*8 + lm8)*KROW + (t8>>1)*16; // +ks*32 (+SM_QL)
    const uint32_t k_off  = ((t8>>1)*8 + lm8)*KROW + (t8&1)*16;  // + np*16*KROW + ks*32
    const uint32_t v_off  = ((t8&1)*8 + lm8)*KROW + (t8>>1)*16;  // + ks4*16*KROW + nd*32

    // hoist Qh A-fragments (8 k-steps x 4 regs)
    uint32_t qh[8][4];
    #pragma unroll
    for (int ks = 0; ks < 8; ks++) ldsm4(qh[ks], q_addr + ks*32);

    float o[16][4];
    #pragma unroll
    for (int f = 0; f < 16; f++) { o[f][0]=0.f; o[f][1]=0.f; o[f][2]=0.f; o[f][3]=0.f; }
    float l0 = 0.f, l1 = 0.f;

    for (int kt = 0; kt < N_/64; kt++) {
        if (kt < N_/64 - 1) {
            kv_prefetch(sb + SM_KV + ((kt+1)&1)*STAGE, tid,
                        kh_b, kl_b, vh_b, vl_b, (kt+1)*64);
            CP_COMMIT();
            CP_WAIT1();
        } else {
            CP_WAIT0();
        }
        __syncthreads();

        const uint32_t base = sb + SM_KV + (kt&1)*STAGE;
        const uint32_t kbh = base, kbl = base + 17408;
        const uint32_t vbh = base + 34816, vbl = base + 52224;

        // ---- S = Qh*Kh + Qh*Kl + Ql*Kh  (8 n-frags of 8 keys) ----
        float s[8][4];
        #pragma unroll
        for (int f = 0; f < 8; f++) { s[f][0]=0.f; s[f][1]=0.f; s[f][2]=0.f; s[f][3]=0.f; }

        #pragma unroll
        for (int ks = 0; ks < 8; ks++) {
            uint32_t qlf[4];
            ldsm4(qlf, q_addr + SM_QL + ks*32);
            #pragma unroll
            for (int np = 0; np < 4; np++) {
                uint32_t bh[4], bl[4];
                uint32_t ka = k_off + np*16*KROW + ks*32;
                ldsm4(bh, kbh + ka);
                ldsm4(bl, kbl + ka);
                mma16816(s[2*np],   qh[ks], bh[0], bh[1]);
                mma16816(s[2*np],   qh[ks], bl[0], bl[1]);
                mma16816(s[2*np],   qlf,    bh[0], bh[1]);
                mma16816(s[2*np+1], qh[ks], bh[2], bh[3]);
                mma16816(s[2*np+1], qh[ks], bl[2], bl[3]);
                mma16816(s[2*np+1], qlf,    bh[2], bh[3]);
            }
        }

        // ---- exp2, rowsum, P hi/lo A-frags (in regs), O += P*V ----
        #pragma unroll
        for (int ks4 = 0; ks4 < 4; ks4++) {          // 16-key chunks
            uint32_t ah[4], al[4];
            #pragma unroll
            for (int fi = 0; fi < 2; fi++) {
                float* sf = s[2*ks4 + fi];
                float e0 = ex2f(sf[0]), e1 = ex2f(sf[1]);
                float e2 = ex2f(sf[2]), e3 = ex2f(sf[3]);
                l0 += e0 + e1;  l1 += e2 + e3;
                uint32_t h01 = packbf(e0, e1), h23 = packbf(e2, e3);
                float hf0 = __uint_as_float(h01 << 16);
                float hf1 = __uint_as_float(h01 & 0xffff0000u);
                float hf2 = __uint_as_float(h23 << 16);
                float hf3 = __uint_as_float(h23 & 0xffff0000u);
                ah[fi*2+0] = h01;  ah[fi*2+1] = h23;
                al[fi*2+0] = packbf(e0 - hf0, e1 - hf1);
                al[fi*2+1] = packbf(e2 - hf2, e3 - hf3);
            }
            #pragma unroll
            for (int nd = 0; nd < 8; nd++) {         // 16-dim chunks
                uint32_t vh[4], vl[4];
                uint32_t va = v_off + ks4*16*KROW + nd*32;
                ldsm4t(vh, vbh + va);
                ldsm4t(vl, vbl + va);
                mma16816(o[2*nd],   ah, vh[0], vh[1]);
                mma16816(o[2*nd],   ah, vl[0], vl[1]);
                mma16816(o[2*nd],   al, vh[0], vh[1]);
                mma16816(o[2*nd+1], ah, vh[2], vh[3]);
                mma16816(o[2*nd+1], ah, vl[2], vl[3]);
                mma16816(o[2*nd+1], al, vh[2], vh[3]);
            }
        }
        __syncthreads();   // done reading this stage before it is overwritten
    }

    // ---- normalize and write O -> g_o [B][N][C] via smem transpose ----
    l0 += __shfl_xor_sync(0xffffffffu, l0, 1);
    l0 += __shfl_xor_sync(0xffffffffu, l0, 2);
    l1 += __shfl_xor_sync(0xffffffffu, l1, 1);
    l1 += __shfl_xor_sync(0xffffffffu, l1, 2);
    const float inv0 = 1.0f / l0, inv1 = 1.0f / l1;

    float* smO = (float*)(sm + SM_KV);               // [128][132]
    const int row0 = w*16 + (lane >> 2);
    #pragma unroll
    for (int nd = 0; nd < 16; nd++) {
        int col = nd*8 + (lane & 3)*2;
        *(float2*)&smO[row0*132 + col]     = make_float2(o[nd][0]*inv0, o[nd][1]*inv0);
        *(float2*)&smO[(row0+8)*132 + col] = make_float2(o[nd][2]*inv1, o[nd][3]*inv1);
    }
    __syncthreads();
    for (int e = tid; e < 4096; e += 256) {          // 128 rows x 32 float4
        int r = e >> 5, c4 = e & 31;
        float4 v = *(float4*)&smO[r*132 + c4*4];
        *(float4*)(g_o + ((size_t)b*N_ + q0 + r)*C_ + c4*4) = v;
    }
}

// ---------------------------------------------------------------------------
extern "C" void kernel_launch(void* const* d_in, const int* in_sizes, int n_in,
                              void* d_out, int out_size)
{
    const float* x  = (const float*)d_in[0];
    const float* fw = (const float*)d_in[1];
    const float* wq = (const float*)d_in[2];
    const float* bq = (const float*)d_in[3];
    const float* wk = (const float*)d_in[4];
    const float* bk = (const float*)d_in[5];
    const float* wv = (const float*)d_in[6];
    const float* bv = (const float*)d_in[7];
    const float* wo = (const float*)d_in[8];
    const float* bo = (const float*)d_in[9];
    float* out = (float*)d_out;

    float* op;
    cudaGetSymbolAddress((void**)&op, g_o);

    const int proj_smem = 128*132*sizeof(float);
    cudaFuncSetAttribute(proj_qkv_kernel, cudaFuncAttributeMaxDynamicSharedMemorySize, proj_smem);
    cudaFuncSetAttribute(proj_out_kernel, cudaFuncAttributeMaxDynamicSharedMemorySize, proj_smem);
    cudaFuncSetAttribute(attn_mma_kernel, cudaFuncAttributeMaxDynamicSharedMemorySize, ATTN_SMEM);

    dim3 pg(N_/128, B_);
    proj_qkv_kernel<<<pg, 256, proj_smem>>>(x, fw, wq, bq, wk, bk, wv, bv);

    dim3 ag(N_/128, B_);
    attn_mma_kernel<<<ag, 256, ATTN_SMEM>>>();

    proj_out_kernel<<<pg, 256, proj_smem>>>(op, wo, bo, out);
}